// round 1
// baseline (speedup 1.0000x reference)
#include <cuda_runtime.h>
#include <cstdint>
#include <cstddef>

#define BS   256
#define HID  1024
#define NT   100
#define ACT  32
#define KIN  8000
#define G3   3072
#define OUTD 64

// Scratch (allocation-free rule: __device__ globals)
__device__ float g_h0[BS * HID];
__device__ float g_outs[(size_t)NT * BS * HID];   // [t][b][hid], ~105 MB

// Packed fp32x2 FMA — sm_103a FFMA2; ptxas will not auto-fuse this, PTX only.
__device__ __forceinline__ float2 ffma2(float2 a, float2 b, float2 c) {
    union U { float2 f; unsigned long long u; };
    U A, B, C, D;
    A.f = a; B.f = b; C.f = c;
    asm("fma.rn.f32x2 %0, %1, %2, %3;" : "=l"(D.u) : "l"(A.u), "l"(B.u), "l"(C.u));
    return D.f;
}

__device__ __forceinline__ float sigmoidf_(float x) {
    return 1.0f / (1.0f + expf(-x));
}

// ---------------------------------------------------------------------------
// h0 = relu(X[256,8000] @ W_in[8000,1024] + b_in)
// Tile: BM=32, BN=64, BK=32; block (16,16); thread: 2 rows x 4 cols (2 f32x2)
// ---------------------------------------------------------------------------
__global__ void __launch_bounds__(256) k_h0(const float* __restrict__ X,
                                            const float* __restrict__ W,
                                            const float* __restrict__ bias,
                                            float* __restrict__ H0) {
    __shared__ float As[32][33];
    __shared__ float Bs[32][64];
    const int tx = threadIdx.x, ty = threadIdx.y;
    const int tid = ty * 16 + tx;
    const int m0 = blockIdx.y * 32, n0 = blockIdx.x * 64;
    float2 acc[2][2] = {};

    for (int k0 = 0; k0 < KIN; k0 += 32) {
        #pragma unroll
        for (int i = tid; i < 32 * 32; i += 256) {
            int m = i >> 5, k = i & 31;
            As[k][m] = X[(size_t)(m0 + m) * KIN + k0 + k];
        }
        #pragma unroll
        for (int i = tid; i < 32 * 64; i += 256) {
            int k = i >> 6, n = i & 63;
            Bs[k][n] = W[(size_t)(k0 + k) * HID + n0 + n];
        }
        __syncthreads();
        #pragma unroll
        for (int k = 0; k < 32; k++) {
            float a0 = As[k][ty * 2 + 0], a1 = As[k][ty * 2 + 1];
            float2 A0 = make_float2(a0, a0), A1 = make_float2(a1, a1);
            const float2* bp = reinterpret_cast<const float2*>(&Bs[k][tx * 4]);
            float2 b0 = bp[0], b1 = bp[1];
            acc[0][0] = ffma2(A0, b0, acc[0][0]);
            acc[0][1] = ffma2(A0, b1, acc[0][1]);
            acc[1][0] = ffma2(A1, b0, acc[1][0]);
            acc[1][1] = ffma2(A1, b1, acc[1][1]);
        }
        __syncthreads();
    }
    #pragma unroll
    for (int r = 0; r < 2; r++) {
        int m = m0 + ty * 2 + r;
        #pragma unroll
        for (int c = 0; c < 2; c++) {
            int n = n0 + tx * 4 + c * 2;
            float v0 = acc[r][c].x + bias[n];
            float v1 = acc[r][c].y + bias[n + 1];
            H0[(size_t)m * HID + n]     = v0 > 0.f ? v0 : 0.f;
            H0[(size_t)m * HID + n + 1] = v1 > 0.f ? v1 : 0.f;
        }
    }
}

// ---------------------------------------------------------------------------
// One GRU step, fully fused:
//   acc_r/acc_z/acc_hn over h_prev @ Wh (K=1024)
//   + acc_r/acc_z/acc_in over a_t @ Wi   (K=32)
//   gates + blend, write h_t.
// Grid: (HID/64, BS/32) = (16, 8) = 128 blocks (one wave).
// ---------------------------------------------------------------------------
__global__ void __launch_bounds__(256) k_step(const float* __restrict__ hprev,
                                              const float* __restrict__ action, int t,
                                              const float* __restrict__ Wi,
                                              const float* __restrict__ bi,
                                              const float* __restrict__ Wh,
                                              const float* __restrict__ bhn,
                                              float* __restrict__ hout) {
    __shared__ float As[32][33];
    __shared__ float Br[32][64];
    __shared__ float Bz[32][64];
    __shared__ float Bn[32][64];
    const int tx = threadIdx.x, ty = threadIdx.y;
    const int tid = ty * 16 + tx;
    const int m0 = blockIdx.y * 32, n0 = blockIdx.x * 64;

    float2 ar[2][2] = {}, az[2][2] = {}, ahn[2][2] = {}, ain[2][2] = {};

    // -- recurrent part: h_prev @ Wh, three gate column blocks per tile --
    for (int k0 = 0; k0 < HID; k0 += 32) {
        #pragma unroll
        for (int i = tid; i < 32 * 32; i += 256) {
            int m = i >> 5, k = i & 31;
            As[k][m] = hprev[(size_t)(m0 + m) * HID + k0 + k];
        }
        #pragma unroll
        for (int i = tid; i < 32 * 64; i += 256) {
            int k = i >> 6, n = i & 63;
            const float* wrow = Wh + (size_t)(k0 + k) * G3 + n0 + n;
            Br[k][n] = wrow[0];
            Bz[k][n] = wrow[HID];
            Bn[k][n] = wrow[2 * HID];
        }
        __syncthreads();
        #pragma unroll
        for (int k = 0; k < 32; k++) {
            float a0 = As[k][ty * 2 + 0], a1 = As[k][ty * 2 + 1];
            float2 A0 = make_float2(a0, a0), A1 = make_float2(a1, a1);
            const float2* brp = reinterpret_cast<const float2*>(&Br[k][tx * 4]);
            const float2* bzp = reinterpret_cast<const float2*>(&Bz[k][tx * 4]);
            const float2* bnp = reinterpret_cast<const float2*>(&Bn[k][tx * 4]);
            float2 br0 = brp[0], br1 = brp[1];
            float2 bz0 = bzp[0], bz1 = bzp[1];
            float2 bn0 = bnp[0], bn1 = bnp[1];
            ar[0][0]  = ffma2(A0, br0, ar[0][0]);  ar[0][1]  = ffma2(A0, br1, ar[0][1]);
            ar[1][0]  = ffma2(A1, br0, ar[1][0]);  ar[1][1]  = ffma2(A1, br1, ar[1][1]);
            az[0][0]  = ffma2(A0, bz0, az[0][0]);  az[0][1]  = ffma2(A0, bz1, az[0][1]);
            az[1][0]  = ffma2(A1, bz0, az[1][0]);  az[1][1]  = ffma2(A1, bz1, az[1][1]);
            ahn[0][0] = ffma2(A0, bn0, ahn[0][0]); ahn[0][1] = ffma2(A0, bn1, ahn[0][1]);
            ahn[1][0] = ffma2(A1, bn0, ahn[1][0]); ahn[1][1] = ffma2(A1, bn1, ahn[1][1]);
        }
        __syncthreads();
    }

    // -- input part: a_t @ Wi (K = ACT = 32, single tile) --
    {
        #pragma unroll
        for (int i = tid; i < 32 * 32; i += 256) {
            int m = i >> 5, k = i & 31;
            As[k][m] = action[(size_t)(m0 + m) * NT * ACT + t * ACT + k];
        }
        #pragma unroll
        for (int i = tid; i < 32 * 64; i += 256) {
            int k = i >> 6, n = i & 63;
            const float* wrow = Wi + (size_t)k * G3 + n0 + n;
            Br[k][n] = wrow[0];
            Bz[k][n] = wrow[HID];
            Bn[k][n] = wrow[2 * HID];
        }
        __syncthreads();
        #pragma unroll
        for (int k = 0; k < 32; k++) {
            float a0 = As[k][ty * 2 + 0], a1 = As[k][ty * 2 + 1];
            float2 A0 = make_float2(a0, a0), A1 = make_float2(a1, a1);
            const float2* brp = reinterpret_cast<const float2*>(&Br[k][tx * 4]);
            const float2* bzp = reinterpret_cast<const float2*>(&Bz[k][tx * 4]);
            const float2* bnp = reinterpret_cast<const float2*>(&Bn[k][tx * 4]);
            float2 br0 = brp[0], br1 = brp[1];
            float2 bz0 = bzp[0], bz1 = bzp[1];
            float2 bn0 = bnp[0], bn1 = bnp[1];
            ar[0][0]  = ffma2(A0, br0, ar[0][0]);  ar[0][1]  = ffma2(A0, br1, ar[0][1]);
            ar[1][0]  = ffma2(A1, br0, ar[1][0]);  ar[1][1]  = ffma2(A1, br1, ar[1][1]);
            az[0][0]  = ffma2(A0, bz0, az[0][0]);  az[0][1]  = ffma2(A0, bz1, az[0][1]);
            az[1][0]  = ffma2(A1, bz0, az[1][0]);  az[1][1]  = ffma2(A1, bz1, az[1][1]);
            ain[0][0] = ffma2(A0, bn0, ain[0][0]); ain[0][1] = ffma2(A0, bn1, ain[0][1]);
            ain[1][0] = ffma2(A1, bn0, ain[1][0]); ain[1][1] = ffma2(A1, bn1, ain[1][1]);
        }
    }

    // -- gates + blend --
    #pragma unroll
    for (int r = 0; r < 2; r++) {
        int m = m0 + ty * 2 + r;
        #pragma unroll
        for (int c = 0; c < 2; c++) {
            int n = n0 + tx * 4 + c * 2;
            #pragma unroll
            for (int e = 0; e < 2; e++) {
                int nn = n + e;
                float vr  = e ? ar[r][c].y  : ar[r][c].x;
                float vz  = e ? az[r][c].y  : az[r][c].x;
                float vhn = e ? ahn[r][c].y : ahn[r][c].x;
                float vin = e ? ain[r][c].y : ain[r][c].x;
                float rg = sigmoidf_(vr + bi[nn]);
                float zg = sigmoidf_(vz + bi[HID + nn]);
                float ng = tanhf(vin + bi[2 * HID + nn] + rg * (vhn + bhn[nn]));
                float hp = hprev[(size_t)m * HID + nn];
                hout[(size_t)m * HID + nn] = (1.0f - zg) * ng + zg * hp;
            }
        }
    }
}

// ---------------------------------------------------------------------------
// out[b][t][:] = outs[t][b][:] @ Wo + bo    (M=25600, N=64, K=1024)
// Grid: 800 blocks of BM=32 rows.
// ---------------------------------------------------------------------------
__global__ void __launch_bounds__(256) k_out(const float* __restrict__ outs,
                                             const float* __restrict__ Wo,
                                             const float* __restrict__ bo,
                                             float* __restrict__ out) {
    __shared__ float As[32][33];
    __shared__ float Bs[32][64];
    const int tx = threadIdx.x, ty = threadIdx.y;
    const int tid = ty * 16 + tx;
    const int R0 = blockIdx.x * 32;
    float2 acc[2][2] = {};

    for (int k0 = 0; k0 < HID; k0 += 32) {
        #pragma unroll
        for (int i = tid; i < 32 * 32; i += 256) {
            int m = i >> 5, k = i & 31;
            As[k][m] = outs[(size_t)(R0 + m) * HID + k0 + k];
        }
        #pragma unroll
        for (int i = tid; i < 32 * 64; i += 256) {
            int k = i >> 6, n = i & 63;
            Bs[k][n] = Wo[(size_t)(k0 + k) * OUTD + n];
        }
        __syncthreads();
        #pragma unroll
        for (int k = 0; k < 32; k++) {
            float a0 = As[k][ty * 2 + 0], a1 = As[k][ty * 2 + 1];
            float2 A0 = make_float2(a0, a0), A1 = make_float2(a1, a1);
            const float2* bp = reinterpret_cast<const float2*>(&Bs[k][tx * 4]);
            float2 b0 = bp[0], b1 = bp[1];
            acc[0][0] = ffma2(A0, b0, acc[0][0]);
            acc[0][1] = ffma2(A0, b1, acc[0][1]);
            acc[1][0] = ffma2(A1, b0, acc[1][0]);
            acc[1][1] = ffma2(A1, b1, acc[1][1]);
        }
        __syncthreads();
    }

    #pragma unroll
    for (int r = 0; r < 2; r++) {
        int R = R0 + ty * 2 + r;       // R = t*BS + b
        int tt = R >> 8;
        int b  = R & (BS - 1);
        #pragma unroll
        for (int c = 0; c < 2; c++) {
            int n = tx * 4 + c * 2;
            out[((size_t)b * NT + tt) * OUTD + n]     = acc[r][c].x + bo[n];
            out[((size_t)b * NT + tt) * OUTD + n + 1] = acc[r][c].y + bo[n + 1];
        }
    }
}

extern "C" void kernel_launch(void* const* d_in, const int* in_sizes, int n_in,
                              void* d_out, int out_size) {
    const float* history = (const float*)d_in[0];
    const float* action  = (const float*)d_in[1];
    const float* W_in    = (const float*)d_in[2];
    const float* b_in    = (const float*)d_in[3];
    const float* Wi      = (const float*)d_in[4];
    const float* bi      = (const float*)d_in[5];
    const float* Wh      = (const float*)d_in[6];
    const float* bhn     = (const float*)d_in[7];
    const float* Wo      = (const float*)d_in[8];
    const float* bo      = (const float*)d_in[9];
    float* out = (float*)d_out;

    float* h0buf = nullptr;
    float* outsbuf = nullptr;
    cudaGetSymbolAddress((void**)&h0buf, g_h0);
    cudaGetSymbolAddress((void**)&outsbuf, g_outs);

    dim3 blk(16, 16);
    k_h0<<<dim3(HID / 64, BS / 32), blk>>>(history, W_in, b_in, h0buf);
    for (int t = 0; t < NT; t++) {
        const float* hp = (t == 0) ? h0buf : outsbuf + (size_t)(t - 1) * BS * HID;
        k_step<<<dim3(HID / 64, BS / 32), blk>>>(hp, action, t, Wi, bi, Wh, bhn,
                                                 outsbuf + (size_t)t * BS * HID);
    }
    k_out<<<dim3(NT * BS / 32), blk>>>(outsbuf, Wo, bo, out);
}

// round 2
// speedup vs baseline: 2.4152x; 2.4152x over previous
#include <cuda_runtime.h>
#include <cstdint>
#include <cstddef>

#define BS   256
#define HID  1024
#define NT   100
#define ACT  32
#define KIN  8000
#define G3   3072
#define OUTD 64

// Scratch (allocation-free rule: __device__ globals)
__device__ float g_h0[BS * HID];
__device__ float g_outs[(size_t)NT * BS * HID];   // [t][b][hid]

// Packed fp32x2 FMA — sm_103a FFMA2; PTX-only (ptxas won't auto-fuse).
__device__ __forceinline__ float2 ffma2(float2 a, float2 b, float2 c) {
    union U { float2 f; unsigned long long u; };
    U A, B, C, D;
    A.f = a; B.f = b; C.f = c;
    asm("fma.rn.f32x2 %0, %1, %2, %3;" : "=l"(D.u) : "l"(A.u), "l"(B.u), "l"(C.u));
    return D.f;
}

__device__ __forceinline__ float fast_sigmoid(float x) {
    return __fdividef(1.0f, 1.0f + __expf(-x));
}
// tanh(x) = 1 - 2/(e^{2x}+1); graceful at e=inf (->1) and e=0 (->-1), no NaN.
__device__ __forceinline__ float fast_tanh(float x) {
    float e = __expf(2.0f * x);
    return 1.0f - __fdividef(2.0f, e + 1.0f);
}

#define CP4(dst, src)  asm volatile("cp.async.ca.shared.global [%0], [%1], 4;\n"  :: "r"(dst), "l"(src))
#define CP16(dst, src) asm volatile("cp.async.cg.shared.global [%0], [%1], 16;\n" :: "r"(dst), "l"(src))
#define CP_COMMIT()    asm volatile("cp.async.commit_group;\n")
#define CP_WAIT(n)     asm volatile("cp.async.wait_group %0;\n" :: "n"(n))

// ---------------------------------------------------------------------------
// h0 = relu(X[256,8000] @ W_in[8000,1024] + b_in)   (unchanged from R1)
// ---------------------------------------------------------------------------
__global__ void __launch_bounds__(256) k_h0(const float* __restrict__ X,
                                            const float* __restrict__ W,
                                            const float* __restrict__ bias,
                                            float* __restrict__ H0) {
    __shared__ float As[32][33];
    __shared__ float Bs[32][64];
    const int tx = threadIdx.x, ty = threadIdx.y;
    const int tid = ty * 16 + tx;
    const int m0 = blockIdx.y * 32, n0 = blockIdx.x * 64;
    float2 acc[2][2] = {};

    for (int k0 = 0; k0 < KIN; k0 += 32) {
        #pragma unroll
        for (int i = tid; i < 32 * 32; i += 256) {
            int m = i >> 5, k = i & 31;
            As[k][m] = X[(size_t)(m0 + m) * KIN + k0 + k];
        }
        #pragma unroll
        for (int i = tid; i < 32 * 64; i += 256) {
            int k = i >> 6, n = i & 63;
            Bs[k][n] = W[(size_t)(k0 + k) * HID + n0 + n];
        }
        __syncthreads();
        #pragma unroll
        for (int k = 0; k < 32; k++) {
            float a0 = As[k][ty * 2 + 0], a1 = As[k][ty * 2 + 1];
            float2 A0 = make_float2(a0, a0), A1 = make_float2(a1, a1);
            const float2* bp = reinterpret_cast<const float2*>(&Bs[k][tx * 4]);
            float2 b0 = bp[0], b1 = bp[1];
            acc[0][0] = ffma2(A0, b0, acc[0][0]);
            acc[0][1] = ffma2(A0, b1, acc[0][1]);
            acc[1][0] = ffma2(A1, b0, acc[1][0]);
            acc[1][1] = ffma2(A1, b1, acc[1][1]);
        }
        __syncthreads();
    }
    #pragma unroll
    for (int r = 0; r < 2; r++) {
        int m = m0 + ty * 2 + r;
        #pragma unroll
        for (int c = 0; c < 2; c++) {
            int n = n0 + tx * 4 + c * 2;
            float v0 = acc[r][c].x + bias[n];
            float v1 = acc[r][c].y + bias[n + 1];
            H0[(size_t)m * HID + n]     = v0 > 0.f ? v0 : 0.f;
            H0[(size_t)m * HID + n + 1] = v1 > 0.f ? v1 : 0.f;
        }
    }
}

// ---------------------------------------------------------------------------
// GRU step v2: 512 threads = 4 K-groups x 128 threads (split-K over HID).
// Per-group tile: BM=32 x BN=64(per gate), thread tile 4x4x3, BK=16,
// cp.async double-buffered. Grid (16,8)=128 blocks -> 16 warps/SM.
// ---------------------------------------------------------------------------
#define BK     16
#define KPER   256              // HID / 4 groups
#define NTILES (KPER / BK)      // 16
#define ASZ    (BK * 36)        // 576 floats (pad 36 for 16B-aligned float4 rows)
#define BGATE  (BK * 64)        // 1024 floats per gate
#define BSZ    (3 * BGATE)      // 3072
#define STG    (ASZ + BSZ)      // 3648
#define GRP    (2 * STG)        // 7296 floats per group (2 stages)
#define SMEMF  (4 * GRP)        // 29184 floats = 116,736 B

__global__ void __launch_bounds__(512) k_step2(const float* __restrict__ hprev,
                                               const float* __restrict__ action, int t,
                                               const float* __restrict__ Wi,
                                               const float* __restrict__ bi,
                                               const float* __restrict__ Wh,
                                               const float* __restrict__ bhn,
                                               float* __restrict__ hout) {
    extern __shared__ float sm[];
    const int tid  = threadIdx.x;
    const int g    = tid >> 7;          // K-group 0..3
    const int wtid = tid & 127;
    const int tx   = wtid & 15;         // n-dim (4 cols each)
    const int ty   = wtid >> 4;         // m-dim 0..7 (4 rows each)
    const int m0 = blockIdx.y * 32, n0 = blockIdx.x * 64;
    float* gb = sm + g * GRP;

    float2 acc[3][4][2] = {};           // [gate r/z/hn][row][colpair]

    // ---- stage loader (cp.async) ----
    auto load_tile = [&](int stage, int tl) {
        const int kb = g * KPER + tl * BK;
        float* dstA = gb + stage * STG;
        const float* asrc = hprev + (size_t)m0 * HID + kb;
        #pragma unroll
        for (int i = wtid; i < BK * 32; i += 128) {
            int k = i & 15, m = i >> 4;
            uint32_t d = (uint32_t)__cvta_generic_to_shared(dstA + k * 36 + m);
            CP4(d, asrc + (size_t)m * HID + k);
        }
        const float* bsrc = Wh + (size_t)kb * G3 + n0;
        float* dstB = dstA + ASZ;
        #pragma unroll
        for (int i = wtid; i < 3 * BK * 16; i += 128) {  // 768 float4
            int gate = i >> 8, rem = i & 255, k = rem >> 4, n4 = rem & 15;
            uint32_t d = (uint32_t)__cvta_generic_to_shared(dstB + gate * BGATE + k * 64 + n4 * 4);
            CP16(d, bsrc + (size_t)k * G3 + gate * HID + n4 * 4);
        }
    };

    auto compute = [&](int stage) {
        const float* As_ = gb + stage * STG;
        const float* B_  = As_ + ASZ;
        #pragma unroll
        for (int k = 0; k < BK; k++) {
            float4 a4 = *reinterpret_cast<const float4*>(As_ + k * 36 + ty * 4);
            float2 A0 = make_float2(a4.x, a4.x), A1 = make_float2(a4.y, a4.y);
            float2 A2 = make_float2(a4.z, a4.z), A3 = make_float2(a4.w, a4.w);
            #pragma unroll
            for (int gate = 0; gate < 3; gate++) {
                float4 b = *reinterpret_cast<const float4*>(B_ + gate * BGATE + k * 64 + tx * 4);
                float2 b0 = make_float2(b.x, b.y), b1 = make_float2(b.z, b.w);
                acc[gate][0][0] = ffma2(A0, b0, acc[gate][0][0]);
                acc[gate][0][1] = ffma2(A0, b1, acc[gate][0][1]);
                acc[gate][1][0] = ffma2(A1, b0, acc[gate][1][0]);
                acc[gate][1][1] = ffma2(A1, b1, acc[gate][1][1]);
                acc[gate][2][0] = ffma2(A2, b0, acc[gate][2][0]);
                acc[gate][2][1] = ffma2(A2, b1, acc[gate][2][1]);
                acc[gate][3][0] = ffma2(A3, b0, acc[gate][3][0]);
                acc[gate][3][1] = ffma2(A3, b1, acc[gate][3][1]);
            }
        }
    };

    // ---- main pipeline over Wh (each group its own K range) ----
    load_tile(0, 0);
    CP_COMMIT();
    for (int tl = 0; tl < NTILES; tl++) {
        if (tl + 1 < NTILES) load_tile((tl + 1) & 1, tl + 1);
        CP_COMMIT();
        CP_WAIT(1);
        __syncthreads();
        compute(tl & 1);
        __syncthreads();
    }

    // ---- groups 1..3: dump partials to their smem regions ----
    if (g != 0) {
        float* red = sm + g * GRP;
        #pragma unroll
        for (int gate = 0; gate < 3; gate++)
            #pragma unroll
            for (int r = 0; r < 4; r++) {
                int row = ty * 4 + r;
                *reinterpret_cast<float2*>(red + gate * 2048 + row * 64 + tx * 4)     = acc[gate][r][0];
                *reinterpret_cast<float2*>(red + gate * 2048 + row * 64 + tx * 4 + 2) = acc[gate][r][1];
            }
    }

    // ---- input GEMM a_t @ Wi (K=32), computed by group 0; all threads load ----
    float2 ain[4][2] = {};
    for (int t2 = 0; t2 < 2; t2++) {
        float* As0 = sm;          // group0 stage0 region
        float* B0  = sm + ASZ;
        for (int i = tid; i < BK * 32; i += 512) {
            int k = i & 15, m = i >> 4;
            As0[k * 36 + m] = action[((size_t)(m0 + m) * NT + t) * ACT + t2 * BK + k];
        }
        for (int i = tid; i < 3 * BK * 64; i += 512) {
            int gate = i >> 10, rem = i & 1023, k = rem >> 6, n = rem & 63;
            B0[gate * BGATE + k * 64 + n] = Wi[(size_t)(t2 * BK + k) * G3 + gate * HID + n0 + n];
        }
        __syncthreads();
        if (g == 0) {
            #pragma unroll
            for (int k = 0; k < BK; k++) {
                float4 a4 = *reinterpret_cast<const float4*>(As0 + k * 36 + ty * 4);
                float2 A0 = make_float2(a4.x, a4.x), A1 = make_float2(a4.y, a4.y);
                float2 A2 = make_float2(a4.z, a4.z), A3 = make_float2(a4.w, a4.w);
                // gate r -> acc[0], gate z -> acc[1], gate n -> ain
                #pragma unroll
                for (int gate = 0; gate < 2; gate++) {
                    float4 b = *reinterpret_cast<const float4*>(B0 + gate * BGATE + k * 64 + tx * 4);
                    float2 b0 = make_float2(b.x, b.y), b1 = make_float2(b.z, b.w);
                    acc[gate][0][0] = ffma2(A0, b0, acc[gate][0][0]);
                    acc[gate][0][1] = ffma2(A0, b1, acc[gate][0][1]);
                    acc[gate][1][0] = ffma2(A1, b0, acc[gate][1][0]);
                    acc[gate][1][1] = ffma2(A1, b1, acc[gate][1][1]);
                    acc[gate][2][0] = ffma2(A2, b0, acc[gate][2][0]);
                    acc[gate][2][1] = ffma2(A2, b1, acc[gate][2][1]);
                    acc[gate][3][0] = ffma2(A3, b0, acc[gate][3][0]);
                    acc[gate][3][1] = ffma2(A3, b1, acc[gate][3][1]);
                }
                float4 b = *reinterpret_cast<const float4*>(B0 + 2 * BGATE + k * 64 + tx * 4);
                float2 b0 = make_float2(b.x, b.y), b1 = make_float2(b.z, b.w);
                ain[0][0] = ffma2(A0, b0, ain[0][0]);  ain[0][1] = ffma2(A0, b1, ain[0][1]);
                ain[1][0] = ffma2(A1, b0, ain[1][0]);  ain[1][1] = ffma2(A1, b1, ain[1][1]);
                ain[2][0] = ffma2(A2, b0, ain[2][0]);  ain[2][1] = ffma2(A2, b1, ain[2][1]);
                ain[3][0] = ffma2(A3, b0, ain[3][0]);  ain[3][1] = ffma2(A3, b1, ain[3][1]);
            }
        }
        __syncthreads();
    }

    // ---- epilogue (group 0): reduce partials, gates, blend, store h_t ----
    if (g == 0) {
        float4 bir = *reinterpret_cast<const float4*>(bi + n0 + tx * 4);
        float4 biz = *reinterpret_cast<const float4*>(bi + HID + n0 + tx * 4);
        float4 bin = *reinterpret_cast<const float4*>(bi + 2 * HID + n0 + tx * 4);
        float4 bh  = *reinterpret_cast<const float4*>(bhn + n0 + tx * 4);
        const float birv[4] = {bir.x, bir.y, bir.z, bir.w};
        const float bizv[4] = {biz.x, biz.y, biz.z, biz.w};
        const float binv[4] = {bin.x, bin.y, bin.z, bin.w};
        const float bhv[4]  = {bh.x,  bh.y,  bh.z,  bh.w};

        #pragma unroll
        for (int r = 0; r < 4; r++) {
            const int row = ty * 4 + r;
            const int m   = m0 + row;
            float rr[4] = {acc[0][r][0].x, acc[0][r][0].y, acc[0][r][1].x, acc[0][r][1].y};
            float zz[4] = {acc[1][r][0].x, acc[1][r][0].y, acc[1][r][1].x, acc[1][r][1].y};
            float hn[4] = {acc[2][r][0].x, acc[2][r][0].y, acc[2][r][1].x, acc[2][r][1].y};
            float nn[4] = {ain[r][0].x,    ain[r][0].y,    ain[r][1].x,    ain[r][1].y};
            #pragma unroll
            for (int gg = 1; gg < 4; gg++) {
                const float* red = sm + gg * GRP;
                float4 pr = *reinterpret_cast<const float4*>(red + 0 * 2048 + row * 64 + tx * 4);
                float4 pz = *reinterpret_cast<const float4*>(red + 1 * 2048 + row * 64 + tx * 4);
                float4 pn = *reinterpret_cast<const float4*>(red + 2 * 2048 + row * 64 + tx * 4);
                rr[0] += pr.x; rr[1] += pr.y; rr[2] += pr.z; rr[3] += pr.w;
                zz[0] += pz.x; zz[1] += pz.y; zz[2] += pz.z; zz[3] += pz.w;
                hn[0] += pn.x; hn[1] += pn.y; hn[2] += pn.z; hn[3] += pn.w;
            }
            float4 hp4 = *reinterpret_cast<const float4*>(hprev + (size_t)m * HID + n0 + tx * 4);
            const float hpv[4] = {hp4.x, hp4.y, hp4.z, hp4.w};
            float4 o;
            float* ov = reinterpret_cast<float*>(&o);
            #pragma unroll
            for (int c = 0; c < 4; c++) {
                float rg = fast_sigmoid(rr[c] + birv[c]);
                float zg = fast_sigmoid(zz[c] + bizv[c]);
                float ng = fast_tanh(nn[c] + binv[c] + rg * (hn[c] + bhv[c]));
                ov[c] = (1.0f - zg) * ng + zg * hpv[c];
            }
            *reinterpret_cast<float4*>(hout + (size_t)m * HID + n0 + tx * 4) = o;
        }
    }
}

// ---------------------------------------------------------------------------
// out[b][t][:] = outs[t][b][:] @ Wo + bo    (unchanged from R1)
// ---------------------------------------------------------------------------
__global__ void __launch_bounds__(256) k_out(const float* __restrict__ outs,
                                             const float* __restrict__ Wo,
                                             const float* __restrict__ bo,
                                             float* __restrict__ out) {
    __shared__ float As[32][33];
    __shared__ float Bs[32][64];
    const int tx = threadIdx.x, ty = threadIdx.y;
    const int tid = ty * 16 + tx;
    const int R0 = blockIdx.x * 32;
    float2 acc[2][2] = {};

    for (int k0 = 0; k0 < HID; k0 += 32) {
        #pragma unroll
        for (int i = tid; i < 32 * 32; i += 256) {
            int m = i >> 5, k = i & 31;
            As[k][m] = outs[(size_t)(R0 + m) * HID + k0 + k];
        }
        #pragma unroll
        for (int i = tid; i < 32 * 64; i += 256) {
            int k = i >> 6, n = i & 63;
            Bs[k][n] = Wo[(size_t)(k0 + k) * OUTD + n];
        }
        __syncthreads();
        #pragma unroll
        for (int k = 0; k < 32; k++) {
            float a0 = As[k][ty * 2 + 0], a1 = As[k][ty * 2 + 1];
            float2 A0 = make_float2(a0, a0), A1 = make_float2(a1, a1);
            const float2* bp = reinterpret_cast<const float2*>(&Bs[k][tx * 4]);
            float2 b0 = bp[0], b1 = bp[1];
            acc[0][0] = ffma2(A0, b0, acc[0][0]);
            acc[0][1] = ffma2(A0, b1, acc[0][1]);
            acc[1][0] = ffma2(A1, b0, acc[1][0]);
            acc[1][1] = ffma2(A1, b1, acc[1][1]);
        }
        __syncthreads();
    }

    #pragma unroll
    for (int r = 0; r < 2; r++) {
        int R = R0 + ty * 2 + r;       // R = t*BS + b
        int tt = R >> 8;
        int b  = R & (BS - 1);
        #pragma unroll
        for (int c = 0; c < 2; c++) {
            int n = tx * 4 + c * 2;
            out[((size_t)b * NT + tt) * OUTD + n]     = acc[r][c].x + bo[n];
            out[((size_t)b * NT + tt) * OUTD + n + 1] = acc[r][c].y + bo[n + 1];
        }
    }
}

extern "C" void kernel_launch(void* const* d_in, const int* in_sizes, int n_in,
                              void* d_out, int out_size) {
    const float* history = (const float*)d_in[0];
    const float* action  = (const float*)d_in[1];
    const float* W_in    = (const float*)d_in[2];
    const float* b_in    = (const float*)d_in[3];
    const float* Wi      = (const float*)d_in[4];
    const float* bi      = (const float*)d_in[5];
    const float* Wh      = (const float*)d_in[6];
    const float* bhn     = (const float*)d_in[7];
    const float* Wo      = (const float*)d_in[8];
    const float* bo      = (const float*)d_in[9];
    float* out = (float*)d_out;

    float* h0buf = nullptr;
    float* outsbuf = nullptr;
    cudaGetSymbolAddress((void**)&h0buf, g_h0);
    cudaGetSymbolAddress((void**)&outsbuf, g_outs);

    const int smem_bytes = SMEMF * 4;   // 116,736 B
    cudaFuncSetAttribute(k_step2, cudaFuncAttributeMaxDynamicSharedMemorySize, smem_bytes);

    dim3 blk(16, 16);
    k_h0<<<dim3(HID / 64, BS / 32), blk>>>(history, W_in, b_in, h0buf);
    for (int t = 0; t < NT; t++) {
        const float* hp = (t == 0) ? h0buf : outsbuf + (size_t)(t - 1) * BS * HID;
        k_step2<<<dim3(HID / 64, BS / 32), 512, smem_bytes>>>(hp, action, t, Wi, bi, Wh, bhn,
                                                              outsbuf + (size_t)t * BS * HID);
    }
    k_out<<<dim3(NT * BS / 32), blk>>>(outsbuf, Wo, bo, out);
}

// round 3
// speedup vs baseline: 2.9778x; 1.2329x over previous
#include <cuda_runtime.h>
#include <cstdint>
#include <cstddef>

#define BS   256
#define HID  1024
#define NT   100
#define ACT  32
#define KIN  8000
#define G3   3072
#define OUTD 64

// Scratch (allocation-free rule: __device__ globals)
__device__ float g_h0[BS * HID];
__device__ float g_outs[(size_t)NT * BS * HID];     // [t][b][hid]
__device__ float g_gi[(size_t)NT * BS * G3];        // [t][b][3*HID] = a@Wi + bi

// Packed fp32x2 FMA — sm_103a FFMA2; PTX-only (ptxas won't auto-fuse).
__device__ __forceinline__ float2 ffma2(float2 a, float2 b, float2 c) {
    union U { float2 f; unsigned long long u; };
    U A, B, C, D;
    A.f = a; B.f = b; C.f = c;
    asm("fma.rn.f32x2 %0, %1, %2, %3;" : "=l"(D.u) : "l"(A.u), "l"(B.u), "l"(C.u));
    return D.f;
}

__device__ __forceinline__ float fast_sigmoid(float x) {
    return __fdividef(1.0f, 1.0f + __expf(-x));
}
__device__ __forceinline__ float fast_tanh(float x) {
    float e = __expf(2.0f * x);
    return 1.0f - __fdividef(2.0f, e + 1.0f);
}

#define CP4(dst, src)  asm volatile("cp.async.ca.shared.global [%0], [%1], 4;\n"  :: "r"(dst), "l"(src))
#define CP16(dst, src) asm volatile("cp.async.cg.shared.global [%0], [%1], 16;\n" :: "r"(dst), "l"(src))
#define CP_COMMIT()    asm volatile("cp.async.commit_group;\n")
#define CP_WAIT(n)     asm volatile("cp.async.wait_group %0;\n" :: "n"(n))

// ===========================================================================
// k_gi: GI[t*BS+b][3072] = action[b,t,:] @ Wi + bi    (t-parallel, one shot)
// grid (48, 8, 100), block (16,16)
// ===========================================================================
__global__ void __launch_bounds__(256) k_gi(const float* __restrict__ action,
                                            const float* __restrict__ Wi,
                                            const float* __restrict__ bi,
                                            float* __restrict__ gi) {
    __shared__ float As[32][33];
    __shared__ float Bs[32][64];
    const int tx = threadIdx.x, ty = threadIdx.y;
    const int tid = ty * 16 + tx;
    const int t = blockIdx.z;
    const int b0 = blockIdx.y * 32, n0 = blockIdx.x * 64;

    #pragma unroll
    for (int i = tid; i < 32 * 32; i += 256) {
        int m = i >> 5, k = i & 31;
        As[k][m] = action[(size_t)(b0 + m) * (NT * ACT) + t * ACT + k];
    }
    #pragma unroll
    for (int i = tid; i < 32 * 64; i += 256) {
        int k = i >> 6, n = i & 63;
        Bs[k][n] = Wi[(size_t)k * G3 + n0 + n];
    }
    __syncthreads();

    float2 acc[2][2] = {};
    #pragma unroll
    for (int k = 0; k < 32; k++) {
        float a0 = As[k][ty * 2 + 0], a1 = As[k][ty * 2 + 1];
        float2 A0 = make_float2(a0, a0), A1 = make_float2(a1, a1);
        const float2* bp = reinterpret_cast<const float2*>(&Bs[k][tx * 4]);
        float2 b0v = bp[0], b1v = bp[1];
        acc[0][0] = ffma2(A0, b0v, acc[0][0]);
        acc[0][1] = ffma2(A0, b1v, acc[0][1]);
        acc[1][0] = ffma2(A1, b0v, acc[1][0]);
        acc[1][1] = ffma2(A1, b1v, acc[1][1]);
    }
    #pragma unroll
    for (int r = 0; r < 2; r++) {
        size_t row = (size_t)t * BS + b0 + ty * 2 + r;
        #pragma unroll
        for (int c = 0; c < 2; c++) {
            int n = n0 + tx * 4 + c * 2;
            gi[row * G3 + n]     = acc[r][c].x + bi[n];
            gi[row * G3 + n + 1] = acc[r][c].y + bi[n + 1];
        }
    }
}

// ===========================================================================
// k_h0v2: h0 = relu(X @ W_in + b_in), 512 thr = 4 K-groups, 3-stage cp.async
// grid (16, 8)
// ===========================================================================
#define HBK   16
#define HKPER 2000
#define HNT   125
#define HASZ  (HBK * 36)        // 576
#define HBSZ  (HBK * 64)        // 1024
#define HSTG  (HASZ + HBSZ)     // 1600
#define HGRP  (3 * HSTG)        // 4800
#define HSMF  (4 * HGRP)        // 19200 floats = 76800 B

__global__ void __launch_bounds__(512) k_h0v2(const float* __restrict__ X,
                                              const float* __restrict__ W,
                                              const float* __restrict__ bias,
                                              float* __restrict__ H0) {
    extern __shared__ float sm[];
    const int tid  = threadIdx.x;
    const int g    = tid >> 7;
    const int wtid = tid & 127;
    const int tx   = wtid & 15;
    const int ty   = wtid >> 4;
    const int m0 = blockIdx.y * 32, n0 = blockIdx.x * 64;
    float* gb = sm + g * HGRP;

    float b4x = bias[n0 + (tid & 15) * 4 + 0];
    float b4y = bias[n0 + (tid & 15) * 4 + 1];
    float b4z = bias[n0 + (tid & 15) * 4 + 2];
    float b4w = bias[n0 + (tid & 15) * 4 + 3];

    float2 acc[4][2] = {};

    auto load_tile = [&](int stage, int tl) {
        const int kb = g * HKPER + tl * HBK;
        float* dstA = gb + stage * HSTG;
        const float* asrc = X + (size_t)m0 * KIN + kb;
        #pragma unroll
        for (int i = wtid; i < HBK * 32; i += 128) {
            int k = i & 15, m = i >> 4;
            uint32_t d = (uint32_t)__cvta_generic_to_shared(dstA + k * 36 + m);
            CP4(d, asrc + (size_t)m * KIN + k);
        }
        const float* bsrc = W + (size_t)kb * HID + n0;
        float* dstB = dstA + HASZ;
        #pragma unroll
        for (int i = wtid; i < HBK * 16; i += 128) {
            int k = i >> 4, n4 = i & 15;
            uint32_t d = (uint32_t)__cvta_generic_to_shared(dstB + k * 64 + n4 * 4);
            CP16(d, bsrc + (size_t)k * HID + n4 * 4);
        }
    };

    auto compute = [&](int stage) {
        const float* As_ = gb + stage * HSTG;
        const float* B_  = As_ + HASZ;
        #pragma unroll
        for (int k = 0; k < HBK; k++) {
            float4 a4 = *reinterpret_cast<const float4*>(As_ + k * 36 + ty * 4);
            float2 A0 = make_float2(a4.x, a4.x), A1 = make_float2(a4.y, a4.y);
            float2 A2 = make_float2(a4.z, a4.z), A3 = make_float2(a4.w, a4.w);
            float4 b = *reinterpret_cast<const float4*>(B_ + k * 64 + tx * 4);
            float2 b0 = make_float2(b.x, b.y), b1 = make_float2(b.z, b.w);
            acc[0][0] = ffma2(A0, b0, acc[0][0]); acc[0][1] = ffma2(A0, b1, acc[0][1]);
            acc[1][0] = ffma2(A1, b0, acc[1][0]); acc[1][1] = ffma2(A1, b1, acc[1][1]);
            acc[2][0] = ffma2(A2, b0, acc[2][0]); acc[2][1] = ffma2(A2, b1, acc[2][1]);
            acc[3][0] = ffma2(A3, b0, acc[3][0]); acc[3][1] = ffma2(A3, b1, acc[3][1]);
        }
    };

    load_tile(0, 0); CP_COMMIT();
    load_tile(1, 1); CP_COMMIT();
    int cs = 0, ls = 2;
    for (int tl = 0; tl < HNT; tl++) {
        CP_WAIT(1);
        __syncthreads();
        if (tl + 2 < HNT) load_tile(ls, tl + 2);
        CP_COMMIT();
        compute(cs);
        cs = (cs == 2) ? 0 : cs + 1;
        ls = (ls == 2) ? 0 : ls + 1;
    }

    // partials to own smem region, then parallel reduce+relu
    #pragma unroll
    for (int r = 0; r < 4; r++) {
        float4 v = make_float4(acc[r][0].x, acc[r][0].y, acc[r][1].x, acc[r][1].y);
        *reinterpret_cast<float4*>(gb + (ty * 4 + r) * 64 + tx * 4) = v;
    }
    __syncthreads();

    {
        int row = tid >> 4, c0 = (tid & 15) * 4;
        float s0 = 0.f, s1 = 0.f, s2 = 0.f, s3 = 0.f;
        #pragma unroll
        for (int gg = 0; gg < 4; gg++) {
            float4 p = *reinterpret_cast<const float4*>(sm + gg * HGRP + row * 64 + c0);
            s0 += p.x; s1 += p.y; s2 += p.z; s3 += p.w;
        }
        s0 += b4x; s1 += b4y; s2 += b4z; s3 += b4w;
        float4 o = make_float4(s0 > 0.f ? s0 : 0.f, s1 > 0.f ? s1 : 0.f,
                               s2 > 0.f ? s2 : 0.f, s3 > 0.f ? s3 : 0.f);
        *reinterpret_cast<float4*>(H0 + (size_t)(m0 + row) * HID + n0 + c0) = o;
    }
}

// ===========================================================================
// k_step3: h_t = GRU(h_{t-1}, GI_t). Only h@Wh + gates.
// 512 thr = 4 K-groups x 128; 3-stage cp.async; parallel epilogue.
// grid (16, 8) = 128 blocks
// ===========================================================================
#define BK3    16
#define NTIL3  16               // KPER 256 / 16
#define KPER3  256
#define ASZ3   (BK3 * 36)       // 576
#define BSZ3   (3 * BK3 * 64)   // 3072
#define STG3   (ASZ3 + BSZ3)    // 3648
#define GRP3   (3 * STG3)       // 10944
#define GIOFF  (4 * GRP3)       // 43776
#define HPOFF  (GIOFF + 3 * 2048)
#define SMF3   (HPOFF + 2048)   // 51968 floats = 207872 B

__global__ void __launch_bounds__(512) k_step3(const float* __restrict__ hprev,
                                               const float* __restrict__ gi_t,
                                               const float* __restrict__ Wh,
                                               const float* __restrict__ bhn,
                                               float* __restrict__ hout) {
    extern __shared__ float sm[];
    const int tid  = threadIdx.x;
    const int g    = tid >> 7;
    const int wtid = tid & 127;
    const int tx   = wtid & 15;
    const int ty   = wtid >> 4;
    const int m0 = blockIdx.y * 32, n0 = blockIdx.x * 64;
    float* gb = sm + g * GRP3;

    // bhn into regs (column mapping matches epilogue: (tid&15)*4)
    const int ec0 = (tid & 15) * 4;
    const int erow = tid >> 4;
    float bh0 = bhn[n0 + ec0 + 0], bh1 = bhn[n0 + ec0 + 1];
    float bh2 = bhn[n0 + ec0 + 2], bh3 = bhn[n0 + ec0 + 3];

    // prefetch GI tile (3 gates x 32 x 64) and hprev blend tile (32 x 64)
    {
        uint32_t d = (uint32_t)__cvta_generic_to_shared(sm + HPOFF + erow * 64 + ec0);
        CP16(d, hprev + (size_t)(m0 + erow) * HID + n0 + ec0);
        #pragma unroll
        for (int gate = 0; gate < 3; gate++) {
            uint32_t dg = (uint32_t)__cvta_generic_to_shared(sm + GIOFF + gate * 2048 + erow * 64 + ec0);
            CP16(dg, gi_t + (size_t)(m0 + erow) * G3 + gate * HID + n0 + ec0);
        }
    }
    CP_COMMIT();

    float2 acc[3][4][2] = {};

    auto load_tile = [&](int stage, int tl) {
        const int kb = g * KPER3 + tl * BK3;
        float* dstA = gb + stage * STG3;
        const float* asrc = hprev + (size_t)m0 * HID + kb;
        #pragma unroll
        for (int i = wtid; i < BK3 * 32; i += 128) {
            int k = i & 15, m = i >> 4;
            uint32_t d = (uint32_t)__cvta_generic_to_shared(dstA + k * 36 + m);
            CP4(d, asrc + (size_t)m * HID + k);
        }
        const float* bsrc = Wh + (size_t)kb * G3 + n0;
        float* dstB = dstA + ASZ3;
        #pragma unroll
        for (int i = wtid; i < 3 * BK3 * 16; i += 128) {
            int gate = i >> 8, rem = i & 255, k = rem >> 4, n4 = rem & 15;
            uint32_t d = (uint32_t)__cvta_generic_to_shared(dstB + gate * (BK3 * 64) + k * 64 + n4 * 4);
            CP16(d, bsrc + (size_t)k * G3 + gate * HID + n4 * 4);
        }
    };

    auto compute = [&](int stage) {
        const float* As_ = gb + stage * STG3;
        const float* B_  = As_ + ASZ3;
        #pragma unroll
        for (int k = 0; k < BK3; k++) {
            float4 a4 = *reinterpret_cast<const float4*>(As_ + k * 36 + ty * 4);
            float2 A0 = make_float2(a4.x, a4.x), A1 = make_float2(a4.y, a4.y);
            float2 A2 = make_float2(a4.z, a4.z), A3 = make_float2(a4.w, a4.w);
            #pragma unroll
            for (int gate = 0; gate < 3; gate++) {
                float4 b = *reinterpret_cast<const float4*>(B_ + gate * (BK3 * 64) + k * 64 + tx * 4);
                float2 b0 = make_float2(b.x, b.y), b1 = make_float2(b.z, b.w);
                acc[gate][0][0] = ffma2(A0, b0, acc[gate][0][0]);
                acc[gate][0][1] = ffma2(A0, b1, acc[gate][0][1]);
                acc[gate][1][0] = ffma2(A1, b0, acc[gate][1][0]);
                acc[gate][1][1] = ffma2(A1, b1, acc[gate][1][1]);
                acc[gate][2][0] = ffma2(A2, b0, acc[gate][2][0]);
                acc[gate][2][1] = ffma2(A2, b1, acc[gate][2][1]);
                acc[gate][3][0] = ffma2(A3, b0, acc[gate][3][0]);
                acc[gate][3][1] = ffma2(A3, b1, acc[gate][3][1]);
            }
        }
    };

    load_tile(0, 0); CP_COMMIT();
    load_tile(1, 1); CP_COMMIT();
    int cs = 0, ls = 2;
    #pragma unroll 1
    for (int tl = 0; tl < NTIL3; tl++) {
        CP_WAIT(1);
        __syncthreads();
        if (tl + 2 < NTIL3) load_tile(ls, tl + 2);
        CP_COMMIT();
        compute(cs);
        cs = (cs == 2) ? 0 : cs + 1;
        ls = (ls == 2) ? 0 : ls + 1;
    }

    // each group dumps partials into its own (dead) stage region
    #pragma unroll
    for (int gate = 0; gate < 3; gate++)
        #pragma unroll
        for (int r = 0; r < 4; r++) {
            float4 v = make_float4(acc[gate][r][0].x, acc[gate][r][0].y,
                                   acc[gate][r][1].x, acc[gate][r][1].y);
            *reinterpret_cast<float4*>(gb + gate * 2048 + (ty * 4 + r) * 64 + tx * 4) = v;
        }
    __syncthreads();

    // parallel epilogue: reduce 4 partials, gates, blend, store 4 outputs
    {
        float rr0 = 0.f, rr1 = 0.f, rr2 = 0.f, rr3 = 0.f;
        float zz0 = 0.f, zz1 = 0.f, zz2 = 0.f, zz3 = 0.f;
        float hh0 = 0.f, hh1 = 0.f, hh2 = 0.f, hh3 = 0.f;
        #pragma unroll
        for (int gg = 0; gg < 4; gg++) {
            const float* red = sm + gg * GRP3;
            float4 pr = *reinterpret_cast<const float4*>(red + 0 * 2048 + erow * 64 + ec0);
            float4 pz = *reinterpret_cast<const float4*>(red + 1 * 2048 + erow * 64 + ec0);
            float4 pn = *reinterpret_cast<const float4*>(red + 2 * 2048 + erow * 64 + ec0);
            rr0 += pr.x; rr1 += pr.y; rr2 += pr.z; rr3 += pr.w;
            zz0 += pz.x; zz1 += pz.y; zz2 += pz.z; zz3 += pz.w;
            hh0 += pn.x; hh1 += pn.y; hh2 += pn.z; hh3 += pn.w;
        }
        float4 gr = *reinterpret_cast<const float4*>(sm + GIOFF + 0 * 2048 + erow * 64 + ec0);
        float4 gz = *reinterpret_cast<const float4*>(sm + GIOFF + 1 * 2048 + erow * 64 + ec0);
        float4 gn = *reinterpret_cast<const float4*>(sm + GIOFF + 2 * 2048 + erow * 64 + ec0);
        float4 hp = *reinterpret_cast<const float4*>(sm + HPOFF + erow * 64 + ec0);

        float4 o;
        {
            float rg = fast_sigmoid(rr0 + gr.x);
            float zg = fast_sigmoid(zz0 + gz.x);
            float ng = fast_tanh(gn.x + rg * (hh0 + bh0));
            o.x = (1.0f - zg) * ng + zg * hp.x;
        }
        {
            float rg = fast_sigmoid(rr1 + gr.y);
            float zg = fast_sigmoid(zz1 + gz.y);
            float ng = fast_tanh(gn.y + rg * (hh1 + bh1));
            o.y = (1.0f - zg) * ng + zg * hp.y;
        }
        {
            float rg = fast_sigmoid(rr2 + gr.z);
            float zg = fast_sigmoid(zz2 + gz.z);
            float ng = fast_tanh(gn.z + rg * (hh2 + bh2));
            o.z = (1.0f - zg) * ng + zg * hp.z;
        }
        {
            float rg = fast_sigmoid(rr3 + gr.w);
            float zg = fast_sigmoid(zz3 + gz.w);
            float ng = fast_tanh(gn.w + rg * (hh3 + bh3));
            o.w = (1.0f - zg) * ng + zg * hp.w;
        }
        *reinterpret_cast<float4*>(hout + (size_t)(m0 + erow) * HID + n0 + ec0) = o;
    }
}

// ===========================================================================
// k_out: out[b][t][:] = outs[t][b][:] @ Wo + bo
// ===========================================================================
__global__ void __launch_bounds__(256) k_out(const float* __restrict__ outs,
                                             const float* __restrict__ Wo,
                                             const float* __restrict__ bo,
                                             float* __restrict__ out) {
    __shared__ float As[32][33];
    __shared__ float Bs[32][64];
    const int tx = threadIdx.x, ty = threadIdx.y;
    const int tid = ty * 16 + tx;
    const int R0 = blockIdx.x * 32;
    float2 acc[2][2] = {};

    for (int k0 = 0; k0 < HID; k0 += 32) {
        #pragma unroll
        for (int i = tid; i < 32 * 32; i += 256) {
            int m = i >> 5, k = i & 31;
            As[k][m] = outs[(size_t)(R0 + m) * HID + k0 + k];
        }
        #pragma unroll
        for (int i = tid; i < 32 * 64; i += 256) {
            int k = i >> 6, n = i & 63;
            Bs[k][n] = Wo[(size_t)(k0 + k) * OUTD + n];
        }
        __syncthreads();
        #pragma unroll
        for (int k = 0; k < 32; k++) {
            float a0 = As[k][ty * 2 + 0], a1 = As[k][ty * 2 + 1];
            float2 A0 = make_float2(a0, a0), A1 = make_float2(a1, a1);
            const float2* bp = reinterpret_cast<const float2*>(&Bs[k][tx * 4]);
            float2 b0 = bp[0], b1 = bp[1];
            acc[0][0] = ffma2(A0, b0, acc[0][0]);
            acc[0][1] = ffma2(A0, b1, acc[0][1]);
            acc[1][0] = ffma2(A1, b0, acc[1][0]);
            acc[1][1] = ffma2(A1, b1, acc[1][1]);
        }
        __syncthreads();
    }

    #pragma unroll
    for (int r = 0; r < 2; r++) {
        int R = R0 + ty * 2 + r;       // R = t*BS + b
        int tt = R >> 8;
        int b  = R & (BS - 1);
        #pragma unroll
        for (int c = 0; c < 2; c++) {
            int n = tx * 4 + c * 2;
            out[((size_t)b * NT + tt) * OUTD + n]     = acc[r][c].x + bo[n];
            out[((size_t)b * NT + tt) * OUTD + n + 1] = acc[r][c].y + bo[n + 1];
        }
    }
}

extern "C" void kernel_launch(void* const* d_in, const int* in_sizes, int n_in,
                              void* d_out, int out_size) {
    const float* history = (const float*)d_in[0];
    const float* action  = (const float*)d_in[1];
    const float* W_in    = (const float*)d_in[2];
    const float* b_in    = (const float*)d_in[3];
    const float* Wi      = (const float*)d_in[4];
    const float* bi      = (const float*)d_in[5];
    const float* Wh      = (const float*)d_in[6];
    const float* bhn     = (const float*)d_in[7];
    const float* Wo      = (const float*)d_in[8];
    const float* bo      = (const float*)d_in[9];
    float* out = (float*)d_out;

    float *h0buf = nullptr, *outsbuf = nullptr, *gibuf = nullptr;
    cudaGetSymbolAddress((void**)&h0buf, g_h0);
    cudaGetSymbolAddress((void**)&outsbuf, g_outs);
    cudaGetSymbolAddress((void**)&gibuf, g_gi);

    const int smem_step = SMF3 * 4;   // 207,872 B
    const int smem_h0   = HSMF * 4;   // 76,800 B
    cudaFuncSetAttribute(k_step3, cudaFuncAttributeMaxDynamicSharedMemorySize, smem_step);
    cudaFuncSetAttribute(k_h0v2, cudaFuncAttributeMaxDynamicSharedMemorySize, smem_h0);

    k_h0v2<<<dim3(HID / 64, BS / 32), 512, smem_h0>>>(history, W_in, b_in, h0buf);
    k_gi<<<dim3(G3 / 64, BS / 32, NT), dim3(16, 16)>>>(action, Wi, bi, gibuf);

    for (int t = 0; t < NT; t++) {
        const float* hp = (t == 0) ? h0buf : outsbuf + (size_t)(t - 1) * BS * HID;
        k_step3<<<dim3(HID / 64, BS / 32), 512, smem_step>>>(
            hp, gibuf + (size_t)t * BS * G3, Wh, bhn,
            outsbuf + (size_t)t * BS * HID);
    }
    k_out<<<dim3(NT * BS / 32), dim3(16, 16)>>>(outsbuf, Wo, bo, out);
}